// round 10
// baseline (speedup 1.0000x reference)
#include <cuda_runtime.h>
#include <cuda_fp16.h>
#include <cstdint>

#define N_CODES 16384
#define N_TOK   8192
#define DIM     512
#define THRESH  900.0f
#define MARGIN  12.0f
#define SCALE   20.0f
#define INV2S2  (2.0f/(SCALE*SCALE))
#define CAP     1024
#define BM      128
#define BN      256
#define NKC     4                 // 512 bytes / 128B chunks
#define NTILE   32                // 8192/256
#define NG      (NTILE*NKC)
#define A_BYTES 65536u            // 128 rows x 512 int8, resident
#define STGB    32768u            // one B stage: 256 rows x 128B
#define SMEM_DYN (A_BYTES + 3u*STGB)
#define SWZ(o) ((o) ^ (((o)>>3)&0x70))

__device__ __align__(128) int8_t g_A[(size_t)N_TOK*DIM];
__device__ __align__(128) int8_t g_B[(size_t)N_CODES*DIM];
__device__ __align__(16) float g_c2[N_CODES];
__device__ __align__(16) float g_x2[N_TOK];
__device__ int g_ccnt[2*N_TOK];
__device__ int g_cand[(size_t)2*N_TOK*CAP];

__device__ __forceinline__ uint32_t s2u(const void* p){
    uint32_t a;
    asm("{ .reg .u64 t; cvta.to.shared.u64 t, %1; cvt.u32.u64 %0, t; }" : "=r"(a) : "l"(p));
    return a;
}
#define CPASYNC16(d,s) asm volatile("cp.async.cg.shared.global [%0], [%1], 16;" :: "r"(d),"l"(s) : "memory")
#define LDSM4(r0,r1,r2,r3,a) asm volatile("ldmatrix.sync.aligned.m8n8.x4.shared.b16 {%0,%1,%2,%3}, [%4];" \
    : "=r"(r0),"=r"(r1),"=r"(r2),"=r"(r3) : "r"(a))
#define MMAI(c,a,b0,b1) asm volatile( \
    "mma.sync.aligned.m16n8k32.row.col.s32.s8.s8.s32 {%0,%1,%2,%3},{%4,%5,%6,%7},{%8,%9},{%0,%1,%2,%3};" \
    : "+r"((c)[0]),"+r"((c)[1]),"+r"((c)[2]),"+r"((c)[3]) \
    : "r"((a)[0]),"r"((a)[1]),"r"((a)[2]),"r"((a)[3]),"r"(b0),"r"(b1))

// ---- prep: fp32 -> s8 quant + exact fp32 norms + zero counters ------------
__global__ __launch_bounds__(256) void prep(const float* __restrict__ x,
                                            const float* __restrict__ codes){
    int flat = blockIdx.x*256+threadIdx.x;
    if (flat < 2*N_TOK) g_ccnt[flat]=0;
    int w=flat>>5, lane=threadIdx.x&31;
    if (w>=N_TOK+N_CODES) return;
    bool isx = w<N_TOK;
    int row = isx ? w : w-N_TOK;
    const float* src = isx ? x+(size_t)row*DIM : codes+(size_t)row*DIM;
    int8_t* d = isx ? g_A+(size_t)row*DIM : g_B+(size_t)row*DIM;
    float s=0.f;
#pragma unroll
    for (int i=0;i<4;i++){
        float4 v = ((const float4*)src)[lane+32*i];
        int c=(lane+32*i)*4;
        float vv[4]={v.x,v.y,v.z,v.w};
        char q[4];
#pragma unroll
        for (int u=0;u<4;u++){
            int qi=__float2int_rn(vv[u]*SCALE);
            qi = qi>127?127:(qi<-127?-127:qi);
            q[u]=(char)qi;
            s=fmaf(vv[u],vv[u],s);
        }
        *(char4*)(d+c)=make_char4(q[0],q[1],q[2],q[3]);
    }
#pragma unroll
    for (int o=16;o>0;o>>=1) s += __shfl_xor_sync(0xffffffffu,s,o);
    if (lane==0){ if (isx) g_x2[row]=s; else g_c2[row]=s; }
}

// ---- approx IMMA GEMM (A resident, 3-stage B) + prefix-min candidates -----
__device__ __forceinline__ void issue_B(uint32_t sd,int tid,int nbase,int g){
    int it=g/NKC, kc=g%NKC;
    uint32_t st = sd + A_BYTES + (uint32_t)(g%3)*STGB;
    const int8_t* pb = g_B + (size_t)(nbase+it*BN)*DIM + kc*128;
#pragma unroll
    for (int i=0;i<4;i++){
        int id=tid+i*512, r=id>>3, c=id&7;
        CPASYNC16(st + SWZ((uint32_t)(r*128+c*16)), pb + (size_t)r*DIM + c*16);
    }
    asm volatile("cp.async.commit_group;" ::: "memory");
}

__global__ __launch_bounds__(512,1) void nn_imma(){
    extern __shared__ __align__(1024) char dsm[];
    __shared__ __align__(16) float c2s[BN];
    __shared__ float rv[BM][4];
    __shared__ float pfx[BM];
    const uint32_t sd = s2u(dsm);
    const int tid=threadIdx.x, l=tid&31, wid=tid>>5;
    const int wr=wid>>2, wc=wid&3;          // warp 32x64 tile at (wr*32, wc*64)
    const int row0=blockIdx.x*BM;
    const int nbase=blockIdx.y*(N_CODES/2);
    const int half=blockIdx.y;

    int acc[2][8][4];
#pragma unroll
    for (int a=0;a<2;a++)
#pragma unroll
        for (int b=0;b<8;b++)
#pragma unroll
            for (int c=0;c<4;c++) acc[a][b][c]=0;
    if (tid<BM) pfx[tid]=3.4e38f;

    // preload A (128x512B in 4 chunks of 128 rows x 128B) + B stage 0
    {
        const int8_t* pa = g_A + (size_t)row0*DIM;
#pragma unroll
        for (int i=0;i<8;i++){
            int id=tid+i*512;                 // 0..4095 16B units
            int c=id>>10, r=(id>>3)&127, cc=id&7;
            CPASYNC16(sd + (uint32_t)c*16384u + SWZ((uint32_t)(r*128+cc*16)),
                      pa + (size_t)r*DIM + c*128 + cc*16);
        }
        const int8_t* pb = g_B + (size_t)nbase*DIM;
#pragma unroll
        for (int i=0;i<4;i++){
            int id=tid+i*512, r=id>>3, cc=id&7;
            CPASYNC16(sd + A_BYTES + SWZ((uint32_t)(r*128+cc*16)), pb + (size_t)r*DIM + cc*16);
        }
        asm volatile("cp.async.commit_group;" ::: "memory");
    }
    issue_B(sd,tid,nbase,1);

    for (int g=0; g<NG; g++){
        const int it=g/NKC, kc=g%NKC;
        if (g>=NG-2) asm volatile("cp.async.wait_group 0;" ::: "memory");
        else         asm volatile("cp.async.wait_group 1;" ::: "memory");
        __syncthreads();
        if (g+2<NG) issue_B(sd,tid,nbase,g+2);   // 3-stage ring: safe at top
        if (kc==0 && tid<64)
            *(float4*)(c2s+tid*4) = *(const float4*)(g_c2 + nbase + it*BN + tid*4);

        const uint32_t stA = sd + (uint32_t)kc*16384u;
        const uint32_t stB = sd + A_BYTES + (uint32_t)(g%3)*STGB;
#pragma unroll
        for (int kk=0;kk<4;kk++){                 // 4 x k32 = 128 int8
            uint32_t a[2][4];
#pragma unroll
            for (int mt=0;mt<2;mt++){
                uint32_t row=(uint32_t)(wr*32+mt*16+(l&15));
                uint32_t col=(uint32_t)(kk*32+((l>>4)<<4));
                LDSM4(a[mt][0],a[mt][1],a[mt][2],a[mt][3], stA+SWZ(row*128u+col));
            }
#pragma unroll
            for (int nt0=0;nt0<8;nt0+=2){
                int mi=l>>3;
                uint32_t brow=(uint32_t)(wc*64+nt0*8+((mi>>1)<<3)+(l&7));
                uint32_t bcol=(uint32_t)(kk*32+((mi&1)<<4));
                uint32_t b0,b1,b2,b3;
                LDSM4(b0,b1,b2,b3, stB+SWZ(brow*128u+bcol));
                MMAI(acc[0][nt0],a[0],b0,b1);
                MMAI(acc[1][nt0],a[1],b0,b1);
                MMAI(acc[0][nt0+1],a[0],b2,b3);
                MMAI(acc[1][nt0+1],a[1],b2,b3);
            }
        }
        if (kc==NKC-1){
            const int tilen = nbase + it*BN;
            float tmin[2][2];
#pragma unroll
            for (int mt=0;mt<2;mt++){ tmin[mt][0]=3.4e38f; tmin[mt][1]=3.4e38f; }
#pragma unroll
            for (int mt=0;mt<2;mt++)
#pragma unroll
                for (int nt=0;nt<8;nt++){
                    int nl = wc*64 + nt*8 + (l&3)*2;
                    float c2v0=c2s[nl], c2v1=c2s[nl+1];
                    int* c = acc[mt][nt];
                    float v0=fmaf(-INV2S2,(float)c[0],c2v0);
                    float v1=fmaf(-INV2S2,(float)c[1],c2v1);
                    float v2=fmaf(-INV2S2,(float)c[2],c2v0);
                    float v3=fmaf(-INV2S2,(float)c[3],c2v1);
                    c[0]=__float_as_int(v0); c[1]=__float_as_int(v1);
                    c[2]=__float_as_int(v2); c[3]=__float_as_int(v3);
                    tmin[mt][0]=fminf(tmin[mt][0],fminf(v0,v1));
                    tmin[mt][1]=fminf(tmin[mt][1],fminf(v2,v3));
                }
#pragma unroll
            for (int q=1;q<4;q<<=1)
#pragma unroll
                for (int mt=0;mt<2;mt++){
                    tmin[mt][0]=fminf(tmin[mt][0],__shfl_xor_sync(0xffffffffu,tmin[mt][0],q));
                    tmin[mt][1]=fminf(tmin[mt][1],__shfl_xor_sync(0xffffffffu,tmin[mt][1],q));
                }
            if ((l&3)==0){
                int gq=l>>2;
#pragma unroll
                for (int mt=0;mt<2;mt++){
                    rv[wr*32+mt*16+gq][wc]=tmin[mt][0];
                    rv[wr*32+mt*16+gq+8][wc]=tmin[mt][1];
                }
            }
            __syncthreads();
            if (tid<BM){
                float p=fminf(fminf(rv[tid][0],rv[tid][1]),fminf(rv[tid][2],rv[tid][3]));
                pfx[tid]=fminf(pfx[tid],p);
            }
            __syncthreads();
#pragma unroll
            for (int mt=0;mt<2;mt++){
                const int m0 = wr*32 + mt*16 + (l>>2);
                const float th0 = pfx[m0]   + MARGIN;
                const float th8 = pfx[m0+8] + MARGIN;
#pragma unroll
                for (int nt=0;nt<8;nt++){
                    int nl = tilen + wc*64 + nt*8 + (l&3)*2;
                    int* c = acc[mt][nt];
                    if (__int_as_float(c[0])<=th0){ int gi=half*N_TOK+row0+m0;   int p=atomicAdd(&g_ccnt[gi],1); if(p<CAP) g_cand[(size_t)gi*CAP+p]=nl;   }
                    if (__int_as_float(c[1])<=th0){ int gi=half*N_TOK+row0+m0;   int p=atomicAdd(&g_ccnt[gi],1); if(p<CAP) g_cand[(size_t)gi*CAP+p]=nl+1; }
                    if (__int_as_float(c[2])<=th8){ int gi=half*N_TOK+row0+m0+8; int p=atomicAdd(&g_ccnt[gi],1); if(p<CAP) g_cand[(size_t)gi*CAP+p]=nl;   }
                    if (__int_as_float(c[3])<=th8){ int gi=half*N_TOK+row0+m0+8; int p=atomicAdd(&g_ccnt[gi],1); if(p<CAP) g_cand[(size_t)gi*CAP+p]=nl+1; }
                    c[0]=c[1]=c[2]=c[3]=0;
                }
            }
        }
    }
}

// ---- refine: exact fp32 recheck of candidates, warp per token -------------
__global__ __launch_bounds__(256) void refine(const float* __restrict__ x,
                                              const float* __restrict__ codes,
                                              float* __restrict__ out){
    const int t = blockIdx.x*8 + (threadIdx.x>>5);
    const int l = threadIdx.x&31;
    float xr[16];
    {
        const float4* xp = (const float4*)(x + (size_t)t*DIM) + l*4;
#pragma unroll
        for (int u=0;u<4;u++){
            float4 v=xp[u];
            xr[u*4]=v.x; xr[u*4+1]=v.y; xr[u*4+2]=v.z; xr[u*4+3]=v.w;
        }
    }
    const float x2=g_x2[t];
    float bv=3.4e38f; int bi=0x7fffffff;
#pragma unroll
    for (int h=0;h<2;h++){
        const int gi=h*N_TOK+t;
        int cnt=g_ccnt[gi]; if (cnt>CAP) cnt=CAP;
        const int* lst=g_cand+(size_t)gi*CAP;
        for (int j=0;j<cnt;j++){
            int ci=lst[j];
            const float4* cp=(const float4*)(codes+(size_t)ci*DIM)+l*4;
            float s=0.f;
#pragma unroll
            for (int u=0;u<4;u++){
                float4 v=cp[u];
                s=fmaf(xr[u*4],v.x,s); s=fmaf(xr[u*4+1],v.y,s);
                s=fmaf(xr[u*4+2],v.z,s); s=fmaf(xr[u*4+3],v.w,s);
            }
#pragma unroll
            for (int o=16;o>0;o>>=1) s += __shfl_xor_sync(0xffffffffu,s,o);
            float dist = x2 + g_c2[ci] - 2.f*s;
            if (dist<bv || (dist==bv && ci<bi)){ bv=dist; bi=ci; }
        }
    }
    if (l==0) out[t] = (bv<=THRESH) ? (float)bi : -1.0f;
}

extern "C" void kernel_launch(void* const* d_in, const int* in_sizes, int n_in,
                              void* d_out, int out_size){
    const float* x=(const float*)d_in[0];
    const float* codes=(const float*)d_in[1];
    float* out=(float*)d_out;
    cudaFuncSetAttribute(nn_imma, cudaFuncAttributeMaxDynamicSharedMemorySize, SMEM_DYN);
    prep<<<(N_TOK+N_CODES)/8, 256>>>(x, codes);
    dim3 grid(64,2);
    nn_imma<<<grid, 512, SMEM_DYN>>>();
    refine<<<N_TOK/8, 256>>>(x, codes, out);
}

// round 11
// speedup vs baseline: 2.1102x; 2.1102x over previous
#include <cuda_runtime.h>
#include <cuda_fp16.h>
#include <cstdint>

#define N_CODES 16384
#define N_TOK   8192
#define DIM     512
#define THRESH  900.0f
#define MARGIN  8.0f
#define CAP     1024
#define BM      128
#define BN      256
#define NKC     8                 // 512 halves / 64-half (128B) chunks
#define NTILE   32                // 8192/256
#define NG      (NTILE*NKC)
#define THREADS 1024
#define A_BYTES 131072u           // 128 rows x 512 halves, resident
#define STGB    32768u            // one B stage: 256 rows x 128B
#define SMEM_DYN (A_BYTES + 2u*STGB)
#define SWZ(o) ((o) ^ (((o)>>3)&0x70))

__device__ __align__(128) __half g_A[(size_t)N_TOK*DIM];     // x hi
__device__ __align__(128) __half g_B[(size_t)N_CODES*DIM];   // codes hi
__device__ __align__(16) float g_c2[N_CODES];
__device__ __align__(16) float g_x2[N_TOK];
__device__ int g_ccnt[2*N_TOK];
__device__ int g_cand[(size_t)2*N_TOK*CAP];

__device__ __forceinline__ uint32_t s2u(const void* p){
    uint32_t a;
    asm("{ .reg .u64 t; cvta.to.shared.u64 t, %1; cvt.u32.u64 %0, t; }" : "=r"(a) : "l"(p));
    return a;
}
#define CPASYNC16(d,s) asm volatile("cp.async.cg.shared.global [%0], [%1], 16;" :: "r"(d),"l"(s) : "memory")
#define LDSM4(r0,r1,r2,r3,a) asm volatile("ldmatrix.sync.aligned.m8n8.x4.shared.b16 {%0,%1,%2,%3}, [%4];" \
    : "=r"(r0),"=r"(r1),"=r"(r2),"=r"(r3) : "r"(a))
#define MMA(c,a,b0,b1) asm volatile( \
    "mma.sync.aligned.m16n8k16.row.col.f32.f16.f16.f32 {%0,%1,%2,%3},{%4,%5,%6,%7},{%8,%9},{%0,%1,%2,%3};" \
    : "+f"((c)[0]),"+f"((c)[1]),"+f"((c)[2]),"+f"((c)[3]) \
    : "r"((a)[0]),"r"((a)[1]),"r"((a)[2]),"r"((a)[3]),"r"(b0),"r"(b1))

// ---- prep: fp32 -> fp16 + norms + zero candidate counters -----------------
__global__ __launch_bounds__(256) void prep(const float* __restrict__ x,
                                            const float* __restrict__ codes){
    int flat = blockIdx.x*256+threadIdx.x;
    if (flat < 2*N_TOK) g_ccnt[flat]=0;
    int w=flat>>5, lane=threadIdx.x&31;
    if (w>=N_TOK+N_CODES) return;
    bool isx = w<N_TOK;
    int row = isx ? w : w-N_TOK;
    const float* src = isx ? x+(size_t)row*DIM : codes+(size_t)row*DIM;
    __half* d = isx ? g_A+(size_t)row*DIM : g_B+(size_t)row*DIM;
    float s=0.f;
#pragma unroll
    for (int i=0;i<4;i++){
        float4 v = ((const float4*)src)[lane+32*i];
        int c=(lane+32*i)*4;
        float vv[4]={v.x,v.y,v.z,v.w};
        *(__half2*)(d+c)=__floats2half2_rn(vv[0],vv[1]);
        *(__half2*)(d+c+2)=__floats2half2_rn(vv[2],vv[3]);
#pragma unroll
        for (int u=0;u<4;u++) s=fmaf(vv[u],vv[u],s);
    }
#pragma unroll
    for (int o=16;o>0;o>>=1) s += __shfl_xor_sync(0xffffffffu,s,o);
    if (lane==0){ if (isx) g_x2[row]=s; else g_c2[row]=s; }
}

// ---- approx GEMM (A resident, 2-stage B, 32 warps) + candidates -----------
__device__ __forceinline__ void issue_B(uint32_t sd,int tid,int nbase,int g){
    int it=g/NKC, kc=g%NKC;
    uint32_t st = sd + A_BYTES + (uint32_t)(g&1)*STGB;
    const __half* pb = g_B + (size_t)(nbase+it*BN)*DIM + kc*64;
#pragma unroll
    for (int i=0;i<2;i++){
        int id=tid+i*THREADS, r=id>>3, c=id&7;
        CPASYNC16(st + SWZ((uint32_t)(r*128+c*16)), pb + (size_t)r*DIM + c*8);
    }
    asm volatile("cp.async.commit_group;" ::: "memory");
}

__global__ __launch_bounds__(THREADS,1) void nn_hmma(){
    extern __shared__ __align__(1024) char dsm[];
    __shared__ __align__(16) float c2s[BN];
    __shared__ float rv[BM][4];
    const uint32_t sd = s2u(dsm);
    const int tid=threadIdx.x, l=tid&31, wid=tid>>5;
    const int wr=wid>>2, wc=wid&3;          // warp 16x64 tile at (wr*16, wc*64)
    const int row0=blockIdx.x*BM;
    const int nbase=blockIdx.y*(N_CODES/2);
    const int half=blockIdx.y;
    const int m0 = wr*16 + (l>>2);          // this thread's rows: m0, m0+8

    float acc[8][4];
#pragma unroll
    for (int b=0;b<8;b++)
#pragma unroll
        for (int c=0;c<4;c++) acc[b][c]=0.f;
    float pfx0=3.4e38f, pfx1=3.4e38f;

    // preload A (whole 128x512, 8 swizzled 128-row x 128B chunks) + B stage 0
    {
        const __half* pa = g_A + (size_t)row0*DIM;
#pragma unroll
        for (int i=0;i<8;i++){
            int id=tid+i*THREADS;             // 0..8191 16B units
            int c=id>>10, r=(id>>3)&127, cc=id&7;
            CPASYNC16(sd + (uint32_t)c*16384u + SWZ((uint32_t)(r*128+cc*16)),
                      pa + (size_t)r*DIM + c*64 + cc*8);
        }
        const __half* pb = g_B + (size_t)nbase*DIM;
#pragma unroll
        for (int i=0;i<2;i++){
            int id=tid+i*THREADS, r=id>>3, cc=id&7;
            CPASYNC16(sd + A_BYTES + SWZ((uint32_t)(r*128+cc*16)), pb + (size_t)r*DIM + cc*8);
        }
        asm volatile("cp.async.commit_group;" ::: "memory");
    }

    for (int g=0; g<NG; g++){
        const int it=g/NKC, kc=g%NKC;
        asm volatile("cp.async.wait_group 0;" ::: "memory");
        __syncthreads();
        // safe: all warps are past reading buffer (g+1)&1 (used at g-1)
        if (g+1<NG) issue_B(sd,tid,nbase,g+1);
        if (kc==0 && tid<64)
            *(float4*)(c2s+tid*4) = *(const float4*)(g_c2 + nbase + it*BN + tid*4);

        const uint32_t stA = sd + (uint32_t)kc*16384u;
        const uint32_t stB = sd + A_BYTES + (uint32_t)(g&1)*STGB;
#pragma unroll
        for (int kk=0;kk<4;kk++){
            uint32_t a[4];
            {
                uint32_t row=(uint32_t)(wr*16+(l&15));
                uint32_t col=(uint32_t)(kk*32+((l>>4)<<4));
                LDSM4(a[0],a[1],a[2],a[3], stA+SWZ(row*128u+col));
            }
#pragma unroll
            for (int nt0=0;nt0<8;nt0+=2){
                int mi=l>>3;
                uint32_t brow=(uint32_t)(wc*64+nt0*8+((mi>>1)<<3)+(l&7));
                uint32_t bcol=(uint32_t)(kk*32+((mi&1)<<4));
                uint32_t b0,b1,b2,b3;
                LDSM4(b0,b1,b2,b3, stB+SWZ(brow*128u+bcol));
                MMA(acc[nt0],a,b0,b1);
                MMA(acc[nt0+1],a,b2,b3);
            }
        }
        if (kc==NKC-1){
            const int tilen = nbase + it*BN;
            float tmin0=3.4e38f, tmin1=3.4e38f;
#pragma unroll
            for (int nt=0;nt<8;nt++){
                int nl = wc*64 + nt*8 + (l&3)*2;
                float c2v0=c2s[nl], c2v1=c2s[nl+1];
                float* c = acc[nt];
                c[0]=fmaf(-2.f,c[0],c2v0); c[1]=fmaf(-2.f,c[1],c2v1);
                c[2]=fmaf(-2.f,c[2],c2v0); c[3]=fmaf(-2.f,c[3],c2v1);
                tmin0=fminf(tmin0,fminf(c[0],c[1]));
                tmin1=fminf(tmin1,fminf(c[2],c[3]));
            }
            tmin0=fminf(tmin0,__shfl_xor_sync(0xffffffffu,tmin0,1));
            tmin0=fminf(tmin0,__shfl_xor_sync(0xffffffffu,tmin0,2));
            tmin1=fminf(tmin1,__shfl_xor_sync(0xffffffffu,tmin1,1));
            tmin1=fminf(tmin1,__shfl_xor_sync(0xffffffffu,tmin1,2));
            if ((l&3)==0){
                rv[wr*16+(l>>2)][wc]=tmin0;
                rv[wr*16+(l>>2)+8][wc]=tmin1;
            }
            __syncthreads();
            {
                float4 r0=*(const float4*)rv[m0];
                float4 r1=*(const float4*)rv[m0+8];
                pfx0=fminf(pfx0,fminf(fminf(r0.x,r0.y),fminf(r0.z,r0.w)));
                pfx1=fminf(pfx1,fminf(fminf(r1.x,r1.y),fminf(r1.z,r1.w)));
            }
            const float th0=pfx0+MARGIN, th1=pfx1+MARGIN;
            const int gi0=half*N_TOK+row0+m0, gi1=gi0+8;
#pragma unroll
            for (int nt=0;nt<8;nt++){
                int nl = tilen + wc*64 + nt*8 + (l&3)*2;
                float* c = acc[nt];
                if (c[0]<=th0){ int p=atomicAdd(&g_ccnt[gi0],1); if(p<CAP) g_cand[(size_t)gi0*CAP+p]=nl;   }
                if (c[1]<=th0){ int p=atomicAdd(&g_ccnt[gi0],1); if(p<CAP) g_cand[(size_t)gi0*CAP+p]=nl+1; }
                if (c[2]<=th1){ int p=atomicAdd(&g_ccnt[gi1],1); if(p<CAP) g_cand[(size_t)gi1*CAP+p]=nl;   }
                if (c[3]<=th1){ int p=atomicAdd(&g_ccnt[gi1],1); if(p<CAP) g_cand[(size_t)gi1*CAP+p]=nl+1; }
                c[0]=c[1]=c[2]=c[3]=0.f;
            }
        }
    }
}

// ---- refine: exact fp32 recheck of candidates, warp per token -------------
__global__ __launch_bounds__(256) void refine(const float* __restrict__ x,
                                              const float* __restrict__ codes,
                                              float* __restrict__ out){
    const int t = blockIdx.x*8 + (threadIdx.x>>5);
    const int l = threadIdx.x&31;
    float xr[16];
    {
        const float4* xp = (const float4*)(x + (size_t)t*DIM) + l*4;
#pragma unroll
        for (int u=0;u<4;u++){
            float4 v=xp[u];
            xr[u*4]=v.x; xr[u*4+1]=v.y; xr[u*4+2]=v.z; xr[u*4+3]=v.w;
        }
    }
    const float x2=g_x2[t];
    float bv=3.4e38f; int bi=0x7fffffff;
#pragma unroll
    for (int h=0;h<2;h++){
        const int gi=h*N_TOK+t;
        int cnt=g_ccnt[gi]; if (cnt>CAP) cnt=CAP;
        const int* lst=g_cand+(size_t)gi*CAP;
        for (int j=0;j<cnt;j++){
            int ci=lst[j];
            const float4* cp=(const float4*)(codes+(size_t)ci*DIM)+l*4;
            float s=0.f;
#pragma unroll
            for (int u=0;u<4;u++){
                float4 v=cp[u];
                s=fmaf(xr[u*4],v.x,s); s=fmaf(xr[u*4+1],v.y,s);
                s=fmaf(xr[u*4+2],v.z,s); s=fmaf(xr[u*4+3],v.w,s);
            }
#pragma unroll
            for (int o=16;o>0;o>>=1) s += __shfl_xor_sync(0xffffffffu,s,o);
            float dist = x2 + g_c2[ci] - 2.f*s;
            if (dist<bv || (dist==bv && ci<bi)){ bv=dist; bi=ci; }
        }
    }
    if (l==0) out[t] = (bv<=THRESH) ? (float)bi : -1.0f;
}

extern "C" void kernel_launch(void* const* d_in, const int* in_sizes, int n_in,
                              void* d_out, int out_size){
    const float* x=(const float*)d_in[0];
    const float* codes=(const float*)d_in[1];
    float* out=(float*)d_out;
    cudaFuncSetAttribute(nn_hmma, cudaFuncAttributeMaxDynamicSharedMemorySize, SMEM_DYN);
    prep<<<(N_TOK+N_CODES)/8, 256>>>(x, codes);
    dim3 grid(64,2);
    nn_hmma<<<grid, THREADS, SMEM_DYN>>>();
    refine<<<N_TOK/8, 256>>>(x, codes, out);
}

// round 12
// speedup vs baseline: 2.1321x; 1.0104x over previous
#include <cuda_runtime.h>
#include <cuda_fp16.h>
#include <cstdint>

#define N_CODES 16384
#define N_TOK   8192
#define DIM     512
#define THRESH  900.0f
#define MARGIN  16.0f
#define CAP     1024
#define BM      128
#define BN      256
#define NKC     8                 // 512 halves / 64-half (128B) chunks
#define NTILE   32                // 8192/256
#define NG      (NTILE*NKC)
#define A_BYTES 131072u           // 128 rows x 512 halves, resident
#define STGB    32768u            // one B stage: 256 rows x 128B
#define SMEM_DYN (A_BYTES + 2u*STGB)
#define SWZ(o) ((o) ^ (((o)>>3)&0x70))

__device__ __align__(128) __half g_A[(size_t)N_TOK*DIM];     // x hi
__device__ __align__(128) __half g_B[(size_t)N_CODES*DIM];   // codes hi
__device__ __align__(16) float g_c2[N_CODES];
__device__ __align__(16) float g_x2[N_TOK];
__device__ int g_ccnt[2*N_TOK];
__device__ int g_cand[(size_t)2*N_TOK*CAP];

__device__ __forceinline__ uint32_t s2u(const void* p){
    uint32_t a;
    asm("{ .reg .u64 t; cvta.to.shared.u64 t, %1; cvt.u32.u64 %0, t; }" : "=r"(a) : "l"(p));
    return a;
}
#define CPASYNC16(d,s) asm volatile("cp.async.cg.shared.global [%0], [%1], 16;" :: "r"(d),"l"(s) : "memory")
#define LDSM4(r0,r1,r2,r3,a) asm volatile("ldmatrix.sync.aligned.m8n8.x4.shared.b16 {%0,%1,%2,%3}, [%4];" \
    : "=r"(r0),"=r"(r1),"=r"(r2),"=r"(r3) : "r"(a))
// fp16-accumulator HMMA: D,C are 2 regs (f16x2 pairs)
#define MMAH(c,a,b0,b1) asm volatile( \
    "mma.sync.aligned.m16n8k16.row.col.f16.f16.f16.f16 {%0,%1},{%2,%3,%4,%5},{%6,%7},{%0,%1};" \
    : "+r"((c)[0]),"+r"((c)[1]) \
    : "r"((a)[0]),"r"((a)[1]),"r"((a)[2]),"r"((a)[3]),"r"(b0),"r"(b1))

// ---- prep: fp32 -> fp16 + norms + zero candidate counters -----------------
__global__ __launch_bounds__(256) void prep(const float* __restrict__ x,
                                            const float* __restrict__ codes){
    int flat = blockIdx.x*256+threadIdx.x;
    if (flat < 2*N_TOK) g_ccnt[flat]=0;
    int w=flat>>5, lane=threadIdx.x&31;
    if (w>=N_TOK+N_CODES) return;
    bool isx = w<N_TOK;
    int row = isx ? w : w-N_TOK;
    const float* src = isx ? x+(size_t)row*DIM : codes+(size_t)row*DIM;
    __half* d = isx ? g_A+(size_t)row*DIM : g_B+(size_t)row*DIM;
    float s=0.f;
#pragma unroll
    for (int i=0;i<4;i++){
        float4 v = ((const float4*)src)[lane+32*i];
        int c=(lane+32*i)*4;
        float vv[4]={v.x,v.y,v.z,v.w};
        *(__half2*)(d+c)=__floats2half2_rn(vv[0],vv[1]);
        *(__half2*)(d+c+2)=__floats2half2_rn(vv[2],vv[3]);
#pragma unroll
        for (int u=0;u<4;u++) s=fmaf(vv[u],vv[u],s);
    }
#pragma unroll
    for (int o=16;o>0;o>>=1) s += __shfl_xor_sync(0xffffffffu,s,o);
    if (lane==0){ if (isx) g_x2[row]=s; else g_c2[row]=s; }
}

// ---- approx GEMM (A resident, 2-stage B) + prefix-min candidates ----------
__device__ __forceinline__ void issue_B(uint32_t sd,int tid,int nbase,int g){
    int it=g/NKC, kc=g%NKC;
    uint32_t st = sd + A_BYTES + (uint32_t)(g&1)*STGB;
    const __half* pb = g_B + (size_t)(nbase+it*BN)*DIM + kc*64;
#pragma unroll
    for (int i=0;i<4;i++){
        int id=tid+i*512, r=id>>3, c=id&7;
        CPASYNC16(st + SWZ((uint32_t)(r*128+c*16)), pb + (size_t)r*DIM + c*8);
    }
    asm volatile("cp.async.commit_group;" ::: "memory");
}

__global__ __launch_bounds__(512,1) void nn_hmma(){
    extern __shared__ __align__(1024) char dsm[];
    __shared__ __align__(16) float c2s[BN];
    __shared__ float rv[BM][4];
    __shared__ float pfx[BM];
    const uint32_t sd = s2u(dsm);
    const int tid=threadIdx.x, l=tid&31, wid=tid>>5;
    const int wr=wid>>2, wc=wid&3;          // warp 32x64 tile at (wr*32, wc*64)
    const int row0=blockIdx.x*BM;
    const int nbase=blockIdx.y*(N_CODES/2);
    const int half=blockIdx.y;

    uint32_t acc[2][8][2];                  // fp16x2 accumulators
#pragma unroll
    for (int a=0;a<2;a++)
#pragma unroll
        for (int b=0;b<8;b++){ acc[a][b][0]=0u; acc[a][b][1]=0u; }
    if (tid<BM) pfx[tid]=3.4e38f;

    // preload A (whole 128x512 block, swizzled per 64-half chunk) + B stage 0
    {
        const __half* pa = g_A + (size_t)row0*DIM;
#pragma unroll
        for (int i=0;i<16;i++){
            int id=tid+i*512;                 // 0..8191 16B units
            int c=id>>10, r=(id>>3)&127, cc=id&7;
            CPASYNC16(sd + (uint32_t)c*16384u + SWZ((uint32_t)(r*128+cc*16)),
                      pa + (size_t)r*DIM + c*64 + cc*8);
        }
        const __half* pb = g_B + (size_t)nbase*DIM;
#pragma unroll
        for (int i=0;i<4;i++){
            int id=tid+i*512, r=id>>3, cc=id&7;
            CPASYNC16(sd + A_BYTES + SWZ((uint32_t)(r*128+cc*16)), pb + (size_t)r*DIM + cc*8);
        }
        asm volatile("cp.async.commit_group;" ::: "memory");
    }
    issue_B(sd,tid,nbase,1);

    for (int g=0; g<NG; g++){
        const int it=g/NKC, kc=g%NKC;
        if (g>=NG-2) asm volatile("cp.async.wait_group 0;" ::: "memory");
        else         asm volatile("cp.async.wait_group 1;" ::: "memory");
        __syncthreads();
        if (kc==0 && tid<64)
            *(float4*)(c2s+tid*4) = *(const float4*)(g_c2 + nbase + it*BN + tid*4);

        const uint32_t stA = sd + (uint32_t)kc*16384u;
        const uint32_t stB = sd + A_BYTES + (uint32_t)(g&1)*STGB;
#pragma unroll
        for (int kk=0;kk<4;kk++){
            uint32_t a[2][4];
#pragma unroll
            for (int mt=0;mt<2;mt++){
                uint32_t row=(uint32_t)(wr*32+mt*16+(l&15));
                uint32_t col=(uint32_t)(kk*32+((l>>4)<<4));
                LDSM4(a[mt][0],a[mt][1],a[mt][2],a[mt][3], stA+SWZ(row*128u+col));
            }
#pragma unroll
            for (int nt0=0;nt0<8;nt0+=2){
                int mi=l>>3;
                uint32_t brow=(uint32_t)(wc*64+nt0*8+((mi>>1)<<3)+(l&7));
                uint32_t bcol=(uint32_t)(kk*32+((mi&1)<<4));
                uint32_t b0,b1,b2,b3;
                LDSM4(b0,b1,b2,b3, stB+SWZ(brow*128u+bcol));
                MMAH(acc[0][nt0],a[0],b0,b1);
                MMAH(acc[1][nt0],a[1],b0,b1);
                MMAH(acc[0][nt0+1],a[0],b2,b3);
                MMAH(acc[1][nt0+1],a[1],b2,b3);
            }
        }
        if (kc==NKC-1){
            const int tilen = nbase + it*BN;
            float vbuf[2][8][4];
            float tmin[2][2];
#pragma unroll
            for (int mt=0;mt<2;mt++){ tmin[mt][0]=3.4e38f; tmin[mt][1]=3.4e38f; }
#pragma unroll
            for (int mt=0;mt<2;mt++)
#pragma unroll
                for (int nt=0;nt<8;nt++){
                    int nl = wc*64 + nt*8 + (l&3)*2;
                    float c2v0=c2s[nl], c2v1=c2s[nl+1];
                    float2 f0=__half22float2(*(__half2*)&acc[mt][nt][0]); // row m0
                    float2 f1=__half22float2(*(__half2*)&acc[mt][nt][1]); // row m0+8
                    float v0=fmaf(-2.f,f0.x,c2v0), v1=fmaf(-2.f,f0.y,c2v1);
                    float v2=fmaf(-2.f,f1.x,c2v0), v3=fmaf(-2.f,f1.y,c2v1);
                    vbuf[mt][nt][0]=v0; vbuf[mt][nt][1]=v1;
                    vbuf[mt][nt][2]=v2; vbuf[mt][nt][3]=v3;
                    tmin[mt][0]=fminf(tmin[mt][0],fminf(v0,v1));
                    tmin[mt][1]=fminf(tmin[mt][1],fminf(v2,v3));
                    acc[mt][nt][0]=0u; acc[mt][nt][1]=0u;
                }
#pragma unroll
            for (int q=1;q<4;q<<=1)
#pragma unroll
                for (int mt=0;mt<2;mt++){
                    tmin[mt][0]=fminf(tmin[mt][0],__shfl_xor_sync(0xffffffffu,tmin[mt][0],q));
                    tmin[mt][1]=fminf(tmin[mt][1],__shfl_xor_sync(0xffffffffu,tmin[mt][1],q));
                }
            if ((l&3)==0){
                int gq=l>>2;
#pragma unroll
                for (int mt=0;mt<2;mt++){
                    rv[wr*32+mt*16+gq][wc]=tmin[mt][0];
                    rv[wr*32+mt*16+gq+8][wc]=tmin[mt][1];
                }
            }
            __syncthreads();
            if (tid<BM){
                float p=fminf(fminf(rv[tid][0],rv[tid][1]),fminf(rv[tid][2],rv[tid][3]));
                pfx[tid]=fminf(pfx[tid],p);
            }
            __syncthreads();
#pragma unroll
            for (int mt=0;mt<2;mt++){
                const int m0 = wr*32 + mt*16 + (l>>2);
                const float th0 = pfx[m0]   + MARGIN;
                const float th8 = pfx[m0+8] + MARGIN;
#pragma unroll
                for (int nt=0;nt<8;nt++){
                    int nl = tilen + wc*64 + nt*8 + (l&3)*2;
                    float* v = vbuf[mt][nt];
                    if (v[0]<=th0){ int gi=half*N_TOK+row0+m0;   int p=atomicAdd(&g_ccnt[gi],1); if(p<CAP) g_cand[(size_t)gi*CAP+p]=nl;   }
                    if (v[1]<=th0){ int gi=half*N_TOK+row0+m0;   int p=atomicAdd(&g_ccnt[gi],1); if(p<CAP) g_cand[(size_t)gi*CAP+p]=nl+1; }
                    if (v[2]<=th8){ int gi=half*N_TOK+row0+m0+8; int p=atomicAdd(&g_ccnt[gi],1); if(p<CAP) g_cand[(size_t)gi*CAP+p]=nl;   }
                    if (v[3]<=th8){ int gi=half*N_TOK+row0+m0+8; int p=atomicAdd(&g_ccnt[gi],1); if(p<CAP) g_cand[(size_t)gi*CAP+p]=nl+1; }
                }
            }
        }
        // 2-stage ring: prefetch g+2 only after all warps finished stage g&1
        __syncthreads();
        if (g+2<NG) issue_B(sd,tid,nbase,g+2);
    }
}

// ---- refine: exact fp32 recheck of candidates, warp per token -------------
__global__ __launch_bounds__(256) void refine(const float* __restrict__ x,
                                              const float* __restrict__ codes,
                                              float* __restrict__ out){
    const int t = blockIdx.x*8 + (threadIdx.x>>5);
    const int l = threadIdx.x&31;
    float xr[16];
    {
        const float4* xp = (const float4*)(x + (size_t)t*DIM) + l*4;
#pragma unroll
        for (int u=0;u<4;u++){
            float4 v=xp[u];
            xr[u*4]=v.x; xr[u*4+1]=v.y; xr[u*4+2]=v.z; xr[u*4+3]=v.w;
        }
    }
    const float x2=g_x2[t];
    float bv=3.4e38f; int bi=0x7fffffff;
#pragma unroll
    for (int h=0;h<2;h++){
        const int gi=h*N_TOK+t;
        int cnt=g_ccnt[gi]; if (cnt>CAP) cnt=CAP;
        const int* lst=g_cand+(size_t)gi*CAP;
        for (int j=0;j<cnt;j++){
            int ci=lst[j];
            const float4* cp=(const float4*)(codes+(size_t)ci*DIM)+l*4;
            float s=0.f;
#pragma unroll
            for (int u=0;u<4;u++){
                float4 v=cp[u];
                s=fmaf(xr[u*4],v.x,s); s=fmaf(xr[u*4+1],v.y,s);
                s=fmaf(xr[u*4+2],v.z,s); s=fmaf(xr[u*4+3],v.w,s);
            }
#pragma unroll
            for (int o=16;o>0;o>>=1) s += __shfl_xor_sync(0xffffffffu,s,o);
            float dist = x2 + g_c2[ci] - 2.f*s;
            if (dist<bv || (dist==bv && ci<bi)){ bv=dist; bi=ci; }
        }
    }
    if (l==0) out[t] = (bv<=THRESH) ? (float)bi : -1.0f;
}

extern "C" void kernel_launch(void* const* d_in, const int* in_sizes, int n_in,
                              void* d_out, int out_size){
    const float* x=(const float*)d_in[0];
    const float* codes=(const float*)d_in[1];
    float* out=(float*)d_out;
    cudaFuncSetAttribute(nn_hmma, cudaFuncAttributeMaxDynamicSharedMemorySize, SMEM_DYN);
    prep<<<(N_TOK+N_CODES)/8, 256>>>(x, codes);
    dim3 grid(64,2);
    nn_hmma<<<grid, 512, SMEM_DYN>>>();
    refine<<<N_TOK/8, 256>>>(x, codes, out);
}

// round 13
// speedup vs baseline: 2.1357x; 1.0017x over previous
#include <cuda_runtime.h>
#include <cuda_fp16.h>
#include <cstdint>

#define N_CODES 16384
#define N_TOK   8192
#define DIM     512
#define THRESH  900.0f
#define MARGIN  16.0f
#define CAP     1024
#define BM      128
#define BN      256
#define NKC     8                 // 512 halves / 64-half (128B) chunks
#define NTILE   32                // 8192/256
#define NG      (NTILE*NKC)
#define A_BYTES 131072u           // 128 rows x 512 halves, resident
#define STGB    32768u            // one B stage: 256 rows x 128B
#define SMEM_DYN (A_BYTES + 2u*STGB)
#define SWZ(o) ((o) ^ (((o)>>3)&0x70))

__device__ __align__(128) __half g_A[(size_t)N_TOK*DIM];     // x hi
__device__ __align__(128) __half g_B[(size_t)N_CODES*DIM];   // codes hi
__device__ __align__(16) float g_c2[N_CODES];
__device__ __align__(16) float g_x2[N_TOK];
__device__ int g_ccnt[2*N_TOK];
__device__ int g_cand[(size_t)2*N_TOK*CAP];

__device__ __forceinline__ uint32_t s2u(const void* p){
    uint32_t a;
    asm("{ .reg .u64 t; cvta.to.shared.u64 t, %1; cvt.u32.u64 %0, t; }" : "=r"(a) : "l"(p));
    return a;
}
#define CPASYNC16(d,s) asm volatile("cp.async.cg.shared.global [%0], [%1], 16;" :: "r"(d),"l"(s) : "memory")
#define LDSM4(r0,r1,r2,r3,a) asm volatile("ldmatrix.sync.aligned.m8n8.x4.shared.b16 {%0,%1,%2,%3}, [%4];" \
    : "=r"(r0),"=r"(r1),"=r"(r2),"=r"(r3) : "r"(a))
// fp16-accumulator HMMA: D,C are 2 regs (f16x2 pairs)
#define MMAH(c,a,b0,b1) asm volatile( \
    "mma.sync.aligned.m16n8k16.row.col.f16.f16.f16.f16 {%0,%1},{%2,%3,%4,%5},{%6,%7},{%0,%1};" \
    : "+r"((c)[0]),"+r"((c)[1]) \
    : "r"((a)[0]),"r"((a)[1]),"r"((a)[2]),"r"((a)[3]),"r"(b0),"r"(b1))

// ---- prep: fp32 -> fp16 + norms + zero candidate counters -----------------
__global__ __launch_bounds__(256) void prep(const float* __restrict__ x,
                                            const float* __restrict__ codes){
    int flat = blockIdx.x*256+threadIdx.x;
    if (flat < 2*N_TOK) g_ccnt[flat]=0;
    int w=flat>>5, lane=threadIdx.x&31;
    if (w>=N_TOK+N_CODES) return;
    bool isx = w<N_TOK;
    int row = isx ? w : w-N_TOK;
    const float* src = isx ? x+(size_t)row*DIM : codes+(size_t)row*DIM;
    __half* d = isx ? g_A+(size_t)row*DIM : g_B+(size_t)row*DIM;
    float s=0.f;
#pragma unroll
    for (int i=0;i<4;i++){
        float4 v = ((const float4*)src)[lane+32*i];
        int c=(lane+32*i)*4;
        float vv[4]={v.x,v.y,v.z,v.w};
        *(__half2*)(d+c)=__floats2half2_rn(vv[0],vv[1]);
        *(__half2*)(d+c+2)=__floats2half2_rn(vv[2],vv[3]);
#pragma unroll
        for (int u=0;u<4;u++) s=fmaf(vv[u],vv[u],s);
    }
#pragma unroll
    for (int o=16;o>0;o>>=1) s += __shfl_xor_sync(0xffffffffu,s,o);
    if (lane==0){ if (isx) g_x2[row]=s; else g_c2[row]=s; }
}

// ---- approx GEMM (A resident, 2-stage B) + prefix-min candidates ----------
__device__ __forceinline__ void issue_B(uint32_t sd,int tid,int nbase,int g){
    int it=g/NKC, kc=g%NKC;
    uint32_t st = sd + A_BYTES + (uint32_t)(g&1)*STGB;
    const __half* pb = g_B + (size_t)(nbase+it*BN)*DIM + kc*64;
#pragma unroll
    for (int i=0;i<4;i++){
        int id=tid+i*512, r=id>>3, c=id&7;
        CPASYNC16(st + SWZ((uint32_t)(r*128+c*16)), pb + (size_t)r*DIM + c*8);
    }
    asm volatile("cp.async.commit_group;" ::: "memory");
}

__global__ __launch_bounds__(512,1) void nn_hmma(){
    extern __shared__ __align__(1024) char dsm[];
    __shared__ __align__(16) float c2s[BN];
    __shared__ float rv[BM][4];
    __shared__ float pfx[BM];
    const uint32_t sd = s2u(dsm);
    const int tid=threadIdx.x, l=tid&31, wid=tid>>5;
    const int wr=wid>>2, wc=wid&3;          // warp 32x64 tile at (wr*32, wc*64)
    const int row0=blockIdx.x*BM;
    const int nbase=blockIdx.y*(N_CODES/2);
    const int half=blockIdx.y;

    uint32_t acc[2][8][2];                  // fp16x2 accumulators
#pragma unroll
    for (int a=0;a<2;a++)
#pragma unroll
        for (int b=0;b<8;b++){ acc[a][b][0]=0u; acc[a][b][1]=0u; }
    if (tid<BM) pfx[tid]=3.4e38f;

    // preload A (whole 128x512 block, swizzled per 64-half chunk) + B stage 0
    {
        const __half* pa = g_A + (size_t)row0*DIM;
#pragma unroll
        for (int i=0;i<16;i++){
            int id=tid+i*512;                 // 0..8191 16B units
            int c=id>>10, r=(id>>3)&127, cc=id&7;
            CPASYNC16(sd + (uint32_t)c*16384u + SWZ((uint32_t)(r*128+cc*16)),
                      pa + (size_t)r*DIM + c*64 + cc*8);
        }
        const __half* pb = g_B + (size_t)nbase*DIM;
#pragma unroll
        for (int i=0;i<4;i++){
            int id=tid+i*512, r=id>>3, cc=id&7;
            CPASYNC16(sd + A_BYTES + SWZ((uint32_t)(r*128+cc*16)), pb + (size_t)r*DIM + cc*8);
        }
        asm volatile("cp.async.commit_group;" ::: "memory");
    }
    issue_B(sd,tid,nbase,1);

    for (int g=0; g<NG; g++){
        const int it=g/NKC, kc=g%NKC;
        if (g>=NG-2) asm volatile("cp.async.wait_group 0;" ::: "memory");
        else         asm volatile("cp.async.wait_group 1;" ::: "memory");
        __syncthreads();
        if (kc==0 && tid<64)
            *(float4*)(c2s+tid*4) = *(const float4*)(g_c2 + nbase + it*BN + tid*4);

        const uint32_t stA = sd + (uint32_t)kc*16384u;
        const uint32_t stB = sd + A_BYTES + (uint32_t)(g&1)*STGB;
#pragma unroll
        for (int kk=0;kk<4;kk++){
            uint32_t a[2][4];
#pragma unroll
            for (int mt=0;mt<2;mt++){
                uint32_t row=(uint32_t)(wr*32+mt*16+(l&15));
                uint32_t col=(uint32_t)(kk*32+((l>>4)<<4));
                LDSM4(a[mt][0],a[mt][1],a[mt][2],a[mt][3], stA+SWZ(row*128u+col));
            }
#pragma unroll
            for (int nt0=0;nt0<8;nt0+=2){
                int mi=l>>3;
                uint32_t brow=(uint32_t)(wc*64+nt0*8+((mi>>1)<<3)+(l&7));
                uint32_t bcol=(uint32_t)(kk*32+((mi&1)<<4));
                uint32_t b0,b1,b2,b3;
                LDSM4(b0,b1,b2,b3, stB+SWZ(brow*128u+bcol));
                MMAH(acc[0][nt0],a[0],b0,b1);
                MMAH(acc[1][nt0],a[1],b0,b1);
                MMAH(acc[0][nt0+1],a[0],b2,b3);
                MMAH(acc[1][nt0+1],a[1],b2,b3);
            }
        }
        if (kc==NKC-1){
            const int tilen = nbase + it*BN;
            float vbuf[2][8][4];
            float tmin[2][2];
#pragma unroll
            for (int mt=0;mt<2;mt++){ tmin[mt][0]=3.4e38f; tmin[mt][1]=3.4e38f; }
#pragma unroll
            for (int mt=0;mt<2;mt++)
#pragma unroll
                for (int nt=0;nt<8;nt++){
                    int nl = wc*64 + nt*8 + (l&3)*2;
                    float c2v0=c2s[nl], c2v1=c2s[nl+1];
                    float2 f0=__half22float2(*(__half2*)&acc[mt][nt][0]); // row m0
                    float2 f1=__half22float2(*(__half2*)&acc[mt][nt][1]); // row m0+8
                    float v0=fmaf(-2.f,f0.x,c2v0), v1=fmaf(-2.f,f0.y,c2v1);
                    float v2=fmaf(-2.f,f1.x,c2v0), v3=fmaf(-2.f,f1.y,c2v1);
                    vbuf[mt][nt][0]=v0; vbuf[mt][nt][1]=v1;
                    vbuf[mt][nt][2]=v2; vbuf[mt][nt][3]=v3;
                    tmin[mt][0]=fminf(tmin[mt][0],fminf(v0,v1));
                    tmin[mt][1]=fminf(tmin[mt][1],fminf(v2,v3));
                    acc[mt][nt][0]=0u; acc[mt][nt][1]=0u;
                }
#pragma unroll
            for (int q=1;q<4;q<<=1)
#pragma unroll
                for (int mt=0;mt<2;mt++){
                    tmin[mt][0]=fminf(tmin[mt][0],__shfl_xor_sync(0xffffffffu,tmin[mt][0],q));
                    tmin[mt][1]=fminf(tmin[mt][1],__shfl_xor_sync(0xffffffffu,tmin[mt][1],q));
                }
            if ((l&3)==0){
                int gq=l>>2;
#pragma unroll
                for (int mt=0;mt<2;mt++){
                    rv[wr*32+mt*16+gq][wc]=tmin[mt][0];
                    rv[wr*32+mt*16+gq+8][wc]=tmin[mt][1];
                }
            }
            __syncthreads();
            if (tid<BM){
                float p=fminf(fminf(rv[tid][0],rv[tid][1]),fminf(rv[tid][2],rv[tid][3]));
                pfx[tid]=fminf(pfx[tid],p);
            }
            __syncthreads();
#pragma unroll
            for (int mt=0;mt<2;mt++){
                const int m0 = wr*32 + mt*16 + (l>>2);
                const float th0 = pfx[m0]   + MARGIN;
                const float th8 = pfx[m0+8] + MARGIN;
#pragma unroll
                for (int nt=0;nt<8;nt++){
                    int nl = tilen + wc*64 + nt*8 + (l&3)*2;
                    float* v = vbuf[mt][nt];
                    if (v[0]<=th0){ int gi=half*N_TOK+row0+m0;   int p=atomicAdd(&g_ccnt[gi],1); if(p<CAP) g_cand[(size_t)gi*CAP+p]=nl;   }
                    if (v[1]<=th0){ int gi=half*N_TOK+row0+m0;   int p=atomicAdd(&g_ccnt[gi],1); if(p<CAP) g_cand[(size_t)gi*CAP+p]=nl+1; }
                    if (v[2]<=th8){ int gi=half*N_TOK+row0+m0+8; int p=atomicAdd(&g_ccnt[gi],1); if(p<CAP) g_cand[(size_t)gi*CAP+p]=nl;   }
                    if (v[3]<=th8){ int gi=half*N_TOK+row0+m0+8; int p=atomicAdd(&g_ccnt[gi],1); if(p<CAP) g_cand[(size_t)gi*CAP+p]=nl+1; }
                }
            }
        }
        // 2-stage ring: prefetch g+2 only after all warps finished stage g&1
        __syncthreads();
        if (g+2<NG) issue_B(sd,tid,nbase,g+2);
    }
}

// ---- refine: exact fp32 recheck of candidates, warp per token -------------
__global__ __launch_bounds__(256) void refine(const float* __restrict__ x,
                                              const float* __restrict__ codes,
                                              float* __restrict__ out){
    const int t = blockIdx.x*8 + (threadIdx.x>>5);
    const int l = threadIdx.x&31;
    float xr[16];
    {
        const float4* xp = (const float4*)(x + (size_t)t*DIM) + l*4;
#pragma unroll
        for (int u=0;u<4;u++){
            float4 v=xp[u];
            xr[u*4]=v.x; xr[u*4+1]=v.y; xr[u*4+2]=v.z; xr[u*4+3]=v.w;
        }
    }
    const float x2=g_x2[t];
    float bv=3.4e38f; int bi=0x7fffffff;
#pragma unroll
    for (int h=0;h<2;h++){
        const int gi=h*N_TOK+t;
        int cnt=g_ccnt[gi]; if (cnt>CAP) cnt=CAP;
        const int* lst=g_cand+(size_t)gi*CAP;
        for (int j=0;j<cnt;j++){
            int ci=lst[j];
            const float4* cp=(const float4*)(codes+(size_t)ci*DIM)+l*4;
            float s=0.f;
#pragma unroll
            for (int u=0;u<4;u++){
                float4 v=cp[u];
                s=fmaf(xr[u*4],v.x,s); s=fmaf(xr[u*4+1],v.y,s);
                s=fmaf(xr[u*4+2],v.z,s); s=fmaf(xr[u*4+3],v.w,s);
            }
#pragma unroll
            for (int o=16;o>0;o>>=1) s += __shfl_xor_sync(0xffffffffu,s,o);
            float dist = x2 + g_c2[ci] - 2.f*s;
            if (dist<bv || (dist==bv && ci<bi)){ bv=dist; bi=ci; }
        }
    }
    if (l==0) out[t] = (bv<=THRESH) ? (float)bi : -1.0f;
}

extern "C" void kernel_launch(void* const* d_in, const int* in_sizes, int n_in,
                              void* d_out, int out_size){
    const float* x=(const float*)d_in[0];
    const float* codes=(const float*)d_in[1];
    float* out=(float*)d_out;
    cudaFuncSetAttribute(nn_hmma, cudaFuncAttributeMaxDynamicSharedMemorySize, SMEM_DYN);
    prep<<<(N_TOK+N_CODES)/8, 256>>>(x, codes);
    dim3 grid(64,2);
    nn_hmma<<<grid, 512, SMEM_DYN>>>();
    refine<<<N_TOK/8, 256>>>(x, codes, out);
}

// round 14
// speedup vs baseline: 2.7091x; 1.2685x over previous
#include <cuda_runtime.h>
#include <cuda_fp16.h>
#include <cstdint>

#define N_CODES 16384
#define N_TOK   8192
#define DIM     512
#define THRESH  900.0f
#define MARGIN  8.0f
#define CAP     1024
#define BM      128
#define BN      256
#define NKC     8                 // kc chunks per n-tile (512/64)
#define NGU     32                // g-iters per unit: 4 n-tiles * 8 kc
#define NUNITS  1024              // 64 token tiles * 16 code slices
#define NCTA    148
#define A_BYTES 131072u
#define STGB    32768u
#define SMEM_DYN (A_BYTES + 2u*STGB)
#define SWZ(o) ((o) ^ (((o)>>3)&0x70))

__device__ __align__(128) __half g_A[(size_t)N_TOK*DIM];
__device__ __align__(128) __half g_B[(size_t)N_CODES*DIM];
__device__ __align__(16) float g_c2[N_CODES];
__device__ __align__(16) float g_x2[N_TOK];
__device__ int g_vmin[N_TOK];     // order-preserving int keys of running min v
__device__ int g_ccnt[N_TOK];
__device__ int g_cand[(size_t)N_TOK*CAP];

__device__ __forceinline__ uint32_t s2u(const void* p){
    uint32_t a;
    asm("{ .reg .u64 t; cvta.to.shared.u64 t, %1; cvt.u32.u64 %0, t; }" : "=r"(a) : "l"(p));
    return a;
}
__device__ __forceinline__ int fkey(float f){ int i=__float_as_int(f); return i<0 ? (i^0x7FFFFFFF) : i; }
__device__ __forceinline__ float funkey(int i){ return __int_as_float(i<0 ? (i^0x7FFFFFFF) : i); }
#define CPASYNC16(d,s) asm volatile("cp.async.cg.shared.global [%0], [%1], 16;" :: "r"(d),"l"(s) : "memory")
#define LDSM4(r0,r1,r2,r3,a) asm volatile("ldmatrix.sync.aligned.m8n8.x4.shared.b16 {%0,%1,%2,%3}, [%4];" \
    : "=r"(r0),"=r"(r1),"=r"(r2),"=r"(r3) : "r"(a))
#define MMA(c,a,b0,b1) asm volatile( \
    "mma.sync.aligned.m16n8k16.row.col.f32.f16.f16.f32 {%0,%1,%2,%3},{%4,%5,%6,%7},{%8,%9},{%0,%1,%2,%3};" \
    : "+f"((c)[0]),"+f"((c)[1]),"+f"((c)[2]),"+f"((c)[3]) \
    : "r"((a)[0]),"r"((a)[1]),"r"((a)[2]),"r"((a)[3]),"r"(b0),"r"(b1))

// ---- prep: fp32 -> fp16 + norms + init vmin/counters -----------------------
__global__ __launch_bounds__(256) void prep(const float* __restrict__ x,
                                            const float* __restrict__ codes){
    int flat = blockIdx.x*256+threadIdx.x;
    if (flat < N_TOK){ g_ccnt[flat]=0; g_vmin[flat]=0x7F800000; }
    int w=flat>>5, lane=threadIdx.x&31;
    if (w>=N_TOK+N_CODES) return;
    bool isx = w<N_TOK;
    int row = isx ? w : w-N_TOK;
    const float* src = isx ? x+(size_t)row*DIM : codes+(size_t)row*DIM;
    __half* d = isx ? g_A+(size_t)row*DIM : g_B+(size_t)row*DIM;
    float s=0.f;
#pragma unroll
    for (int i=0;i<4;i++){
        float4 v = ((const float4*)src)[lane+32*i];
        int c=(lane+32*i)*4;
        float vv[4]={v.x,v.y,v.z,v.w};
        *(__half2*)(d+c)=__floats2half2_rn(vv[0],vv[1]);
        *(__half2*)(d+c+2)=__floats2half2_rn(vv[2],vv[3]);
#pragma unroll
        for (int u=0;u<4;u++) s=fmaf(vv[u],vv[u],s);
    }
#pragma unroll
    for (int o=16;o>0;o>>=1) s += __shfl_xor_sync(0xffffffffu,s,o);
    if (lane==0){ if (isx) g_x2[row]=s; else g_c2[row]=s; }
}

// ---- B stage load: 256 rows x 128B of slice, n-tile (g>>3), kc (g&7) ------
__device__ __forceinline__ void issue_B(uint32_t sd,int tid,int cbase,int g){
    int it=g>>3, kc=g&7;
    uint32_t st = sd + A_BYTES + (uint32_t)(g&1)*STGB;
    const __half* pb = g_B + (size_t)(cbase+it*BN)*DIM + kc*64;
#pragma unroll
    for (int i=0;i<4;i++){
        int id=tid+i*512, r=id>>3, c=id&7;
        CPASYNC16(st + SWZ((uint32_t)(r*128+c*16)), pb + (size_t)r*DIM + c*8);
    }
    asm volatile("cp.async.commit_group;" ::: "memory");
}

__global__ __launch_bounds__(512,1) void nn_hmma(){
    extern __shared__ __align__(1024) char dsm[];
    __shared__ __align__(16) float c2s[BN];
    __shared__ float rv[BM][4];
    __shared__ float pfx[BM];
    const uint32_t sd = s2u(dsm);
    const int tid=threadIdx.x, l=tid&31, wid=tid>>5;
    const int wr=wid>>2, wc=wid&3;          // warp 32x64 tile at (wr*32, wc*64)
    const int bid=blockIdx.x;

    const int ustart = (bid*NUNITS)/NCTA;
    const int uend   = ((bid+1)*NUNITS)/NCTA;
    int cur_tile = -1;

    for (int u=ustart; u<uend; u++){
        const int tile  = u >> 4;
        const int cbase = (u & 15) * 1024;
        const int row0  = tile * BM;

        float acc[2][8][4];
#pragma unroll
        for (int a=0;a<2;a++)
#pragma unroll
            for (int b=0;b<8;b++)
#pragma unroll
                for (int c=0;c<4;c++) acc[a][b][c]=0.f;

        // preload: A (only on tile change) piggybacks in B-group 0
        if (tile != cur_tile){
            cur_tile = tile;
            const __half* pa = g_A + (size_t)row0*DIM;
#pragma unroll
            for (int i=0;i<16;i++){
                int id=tid+i*512;
                int c=id>>10, r=(id>>3)&127, cc=id&7;
                CPASYNC16(sd + (uint32_t)c*16384u + SWZ((uint32_t)(r*128+cc*16)),
                          pa + (size_t)r*DIM + c*64 + cc*8);
            }
        }
        issue_B(sd,tid,cbase,0);
        issue_B(sd,tid,cbase,1);

        for (int g=0; g<NGU; g++){
            const int it=g>>3, kc=g&7;
            if (g>=NGU-2) asm volatile("cp.async.wait_group 0;" ::: "memory");
            else          asm volatile("cp.async.wait_group 1;" ::: "memory");
            __syncthreads();
            if (kc==0 && tid<64)
                *(float4*)(c2s+tid*4) = *(const float4*)(g_c2 + cbase + it*BN + tid*4);

            const uint32_t stA = sd + (uint32_t)kc*16384u;
            const uint32_t stB = sd + A_BYTES + (uint32_t)(g&1)*STGB;
#pragma unroll
            for (int kk=0;kk<4;kk++){
                uint32_t a[2][4];
#pragma unroll
                for (int mt=0;mt<2;mt++){
                    uint32_t row=(uint32_t)(wr*32+mt*16+(l&15));
                    uint32_t col=(uint32_t)(kk*32+((l>>4)<<4));
                    LDSM4(a[mt][0],a[mt][1],a[mt][2],a[mt][3], stA+SWZ(row*128u+col));
                }
#pragma unroll
                for (int nt0=0;nt0<8;nt0+=2){
                    int mi=l>>3;
                    uint32_t brow=(uint32_t)(wc*64+nt0*8+((mi>>1)<<3)+(l&7));
                    uint32_t bcol=(uint32_t)(kk*32+((mi&1)<<4));
                    uint32_t b0,b1,b2,b3;
                    LDSM4(b0,b1,b2,b3, stB+SWZ(brow*128u+bcol));
                    MMA(acc[0][nt0],a[0],b0,b1);
                    MMA(acc[1][nt0],a[1],b0,b1);
                    MMA(acc[0][nt0+1],a[0],b2,b3);
                    MMA(acc[1][nt0+1],a[1],b2,b3);
                }
            }
            if (kc==NKC-1){
                const int tilen = cbase + it*BN;
                float tmin[2][2];
#pragma unroll
                for (int mt=0;mt<2;mt++){ tmin[mt][0]=3.4e38f; tmin[mt][1]=3.4e38f; }
#pragma unroll
                for (int mt=0;mt<2;mt++)
#pragma unroll
                    for (int nt=0;nt<8;nt++){
                        int nl = wc*64 + nt*8 + (l&3)*2;
                        float c2v0=c2s[nl], c2v1=c2s[nl+1];
                        float* c = acc[mt][nt];
                        c[0]=fmaf(-2.f,c[0],c2v0); c[1]=fmaf(-2.f,c[1],c2v1);
                        c[2]=fmaf(-2.f,c[2],c2v0); c[3]=fmaf(-2.f,c[3],c2v1);
                        tmin[mt][0]=fminf(tmin[mt][0],fminf(c[0],c[1]));
                        tmin[mt][1]=fminf(tmin[mt][1],fminf(c[2],c[3]));
                    }
#pragma unroll
                for (int q=1;q<4;q<<=1)
#pragma unroll
                    for (int mt=0;mt<2;mt++){
                        tmin[mt][0]=fminf(tmin[mt][0],__shfl_xor_sync(0xffffffffu,tmin[mt][0],q));
                        tmin[mt][1]=fminf(tmin[mt][1],__shfl_xor_sync(0xffffffffu,tmin[mt][1],q));
                    }
                if ((l&3)==0){
                    int gq=l>>2;
#pragma unroll
                    for (int mt=0;mt<2;mt++){
                        rv[wr*32+mt*16+gq][wc]=tmin[mt][0];
                        rv[wr*32+mt*16+gq+8][wc]=tmin[mt][1];
                    }
                }
                __syncthreads();
                if (tid<BM){
                    float p=fminf(fminf(rv[tid][0],rv[tid][1]),fminf(rv[tid][2],rv[tid][3]));
                    // fold into the global per-token running min; use result as threshold base
                    int old = atomicMin(&g_vmin[row0+tid], fkey(p));
                    pfx[tid]=fminf(p, funkey(old));
                }
                __syncthreads();
#pragma unroll
                for (int mt=0;mt<2;mt++){
                    const int m0 = wr*32 + mt*16 + (l>>2);
                    const float th0 = pfx[m0]   + MARGIN;
                    const float th8 = pfx[m0+8] + MARGIN;
                    const int gi0 = row0+m0, gi1 = row0+m0+8;
#pragma unroll
                    for (int nt=0;nt<8;nt++){
                        int nl = tilen + wc*64 + nt*8 + (l&3)*2;
                        float* c = acc[mt][nt];
                        if (c[0]<=th0){ int p=atomicAdd(&g_ccnt[gi0],1); if(p<CAP) g_cand[(size_t)gi0*CAP+p]=nl;   }
                        if (c[1]<=th0){ int p=atomicAdd(&g_ccnt[gi0],1); if(p<CAP) g_cand[(size_t)gi0*CAP+p]=nl+1; }
                        if (c[2]<=th8){ int p=atomicAdd(&g_ccnt[gi1],1); if(p<CAP) g_cand[(size_t)gi1*CAP+p]=nl;   }
                        if (c[3]<=th8){ int p=atomicAdd(&g_ccnt[gi1],1); if(p<CAP) g_cand[(size_t)gi1*CAP+p]=nl+1; }
                        c[0]=c[1]=c[2]=c[3]=0.f;
                    }
                }
            }
            __syncthreads();
            if (g+2<NGU) issue_B(sd,tid,cbase,g+2);
        }
    }
}

// ---- refine: exact fp32 recheck of candidates, warp per token -------------
__global__ __launch_bounds__(256) void refine(const float* __restrict__ x,
                                              const float* __restrict__ codes,
                                              float* __restrict__ out){
    const int t = blockIdx.x*8 + (threadIdx.x>>5);
    const int l = threadIdx.x&31;
    float xr[16];
    {
        const float4* xp = (const float4*)(x + (size_t)t*DIM) + l*4;
#pragma unroll
        for (int u=0;u<4;u++){
            float4 v=xp[u];
            xr[u*4]=v.x; xr[u*4+1]=v.y; xr[u*4+2]=v.z; xr[u*4+3]=v.w;
        }
    }
    const float x2=g_x2[t];
    float bv=3.4e38f; int bi=0x7fffffff;
    int cnt=g_ccnt[t]; if (cnt>CAP) cnt=CAP;
    const int* lst=g_cand+(size_t)t*CAP;
    for (int j=0;j<cnt;j++){
        int ci=lst[j];
        const float4* cp=(const float4*)(codes+(size_t)ci*DIM)+l*4;
        float s=0.f;
#pragma unroll
        for (int u=0;u<4;u++){
            float4 v=cp[u];
            s=fmaf(xr[u*4],v.x,s); s=fmaf(xr[u*4+1],v.y,s);
            s=fmaf(xr[u*4+2],v.z,s); s=fmaf(xr[u*4+3],v.w,s);
        }
#pragma unroll
        for (int o=16;o>0;o>>=1) s += __shfl_xor_sync(0xffffffffu,s,o);
        float dist = x2 + g_c2[ci] - 2.f*s;
        if (dist<bv || (dist==bv && ci<bi)){ bv=dist; bi=ci; }
    }
    if (l==0) out[t] = (bv<=THRESH) ? (float)bi : -1.0f;
}

extern "C" void kernel_launch(void* const* d_in, const int* in_sizes, int n_in,
                              void* d_out, int out_size){
    const float* x=(const float*)d_in[0];
    const float* codes=(const float*)d_in[1];
    float* out=(float*)d_out;
    cudaFuncSetAttribute(nn_hmma, cudaFuncAttributeMaxDynamicSharedMemorySize, SMEM_DYN);
    prep<<<(N_TOK+N_CODES)/8, 256>>>(x, codes);
    nn_hmma<<<NCTA, 512, SMEM_DYN>>>();
    refine<<<N_TOK/8, 256>>>(x, codes, out);
}